// round 6
// baseline (speedup 1.0000x reference)
#include <cuda_runtime.h>
#include <stdint.h>

#define DIM   2048
#define NE    64
#define TOPK  8
#define BT    128            // tokens per CTA
#define NTHR  256
#define KC    32             // k per smem chunk
#define NCHK  (DIM / KC)     // 64
#define SSTR  66             // sc row stride (even -> 8B-aligned f2 stores)
#define LOG2E 1.4426950408889634f

// Transposed weights [k][expert], float4-aligned. 512 KB, L2-resident.
__device__ float4 g_wt4[DIM * (NE / 4)];
__device__ int    g_hist[NE];
__device__ int    g_cnt;

// ---------------- helpers ----------------
__device__ __forceinline__ void ffma2(unsigned long long &d,
                                      unsigned long long a,
                                      unsigned long long b) {
    asm("fma.rn.f32x2 %0, %1, %2, %0;" : "+l"(d) : "l"(a), "l"(b));
}
__device__ __forceinline__ unsigned long long dup2(float w) {
    unsigned long long r;
    asm("mov.b64 %0, {%1, %1};" : "=l"(r) : "f"(w));
    return r;
}
__device__ __forceinline__ float2 ull_as_f2(unsigned long long v) {
    float2 r;
    asm("mov.b64 {%0, %1}, %2;" : "=f"(r.x), "=f"(r.y) : "l"(v));
    return r;
}

// ============================================================
// Prep: transpose gate_weight [64][2048] -> g_wt4 [2048][16xf4];
// zero histogram + ticket. grid 32 x 256.
// ============================================================
__global__ void prep_kernel(const float* __restrict__ gw) {
    __shared__ float ts[64][68];
    const int t = threadIdx.x, blk = blockIdx.x;
    #pragma unroll
    for (int i = 0; i < 4; i++) {
        int idx = t + i * 256;              // 0..1023
        int e = idx >> 4, q = idx & 15;
        float4 f = ((const float4*)gw)[e * 512 + blk * 16 + q];
        ts[e][q * 4 + 0] = f.x; ts[e][q * 4 + 1] = f.y;
        ts[e][q * 4 + 2] = f.z; ts[e][q * 4 + 3] = f.w;
    }
    __syncthreads();
    #pragma unroll
    for (int i = 0; i < 4; i++) {
        int idx = t + i * 256;
        int k = idx >> 4, j = idx & 15;
        g_wt4[(blk * 64 + k) * 16 + j] =
            make_float4(ts[j * 4 + 0][k], ts[j * 4 + 1][k],
                        ts[j * 4 + 2][k], ts[j * 4 + 3][k]);
    }
    if (blk == 0 && t < NE) g_hist[t] = 0;
    if (blk == 0 && t == 0) g_cnt = 0;
}

// ============================================================
// Fused gate kernel. CTA: 128 tokens x 64 experts, 256 threads.
// Thread: 1 token x 32 experts (one expert half), experts packed
// as f32x2. Arithmetic = sequential fp32 FMA chain over k
// ascending per (token, expert) — bitwise identical to the
// passing R1 kernel.
// ============================================================
__global__ void __launch_bounds__(NTHR, 2)
gate_kernel(const float* __restrict__ x,
            const float* __restrict__ bias_in,
            const float* __restrict__ usage_in,
            float* __restrict__ out, int T, float inv_total) {
    extern __shared__ float sm[];
    float* wsm    = sm;                    // [2][KC][64] = 4096 floats
    float* sc     = sm + 4096;             // [128][66]
    float* bias_s = sc + BT * SSTR;        // [64]
    int*   hist_s = (int*)(bias_s + NE);   // [64]
    int*   flag_s = hist_s + NE;

    const int tid  = threadIdx.x;
    const int tp   = tid & 127;            // token within CTA
    const int half = tid >> 7;             // expert half (0/1)
    const long long tb = (long long)blockIdx.x * BT;

    if (tid < NE) { hist_s[tid] = 0; bias_s[tid] = bias_in[tid]; }

    const float* xr = x + (size_t)(tb + tp) * DIM;

    // stage w chunk 0 (8 KB: 512 float4, 2 per thread)
    {
        float4* dst = (float4*)wsm;
        dst[tid]       = g_wt4[tid];
        dst[tid + 256] = g_wt4[tid + 256];
    }

    // prime x (first 4 k)
    float4 xcur = *(const float4*)(xr);

    unsigned long long acc[16];
    #pragma unroll
    for (int j = 0; j < 16; j++) acc[j] = 0ull;

    __syncthreads();

    for (int ch = 0; ch < NCHK; ch++) {
        const int buf = ch & 1;
        const float* wb = wsm + buf * (KC * 64) + half * 32;

        // prefetch next w chunk into regs
        float4 wn0, wn1;
        if (ch + 1 < NCHK) {
            wn0 = g_wt4[(ch + 1) * 512 + tid];
            wn1 = g_wt4[(ch + 1) * 512 + 256 + tid];
        }

        #pragma unroll
        for (int q = 0; q < 8; q++) {
            float4 xc = xcur;
            const int k4 = ch * KC + q * 4 + 4;
            if (k4 < DIM)
                xcur = *(const float4*)(xr + k4);

            float xs4[4] = {xc.x, xc.y, xc.z, xc.w};
            #pragma unroll
            for (int i = 0; i < 4; i++) {
                unsigned long long d = dup2(xs4[i]);
                const ulonglong2* wk =
                    (const ulonglong2*)(wb + (q * 4 + i) * 64);
                #pragma unroll
                for (int j = 0; j < 8; j++) {   // 8 LDS.128 broadcast
                    ulonglong2 wp = wk[j];
                    ffma2(acc[2 * j],     d, wp.x);
                    ffma2(acc[2 * j + 1], d, wp.y);
                }
            }
        }

        // stage next chunk into the other buffer
        if (ch + 1 < NCHK) {
            float4* dst = (float4*)(wsm + (buf ^ 1) * (KC * 64));
            dst[tid]       = wn0;
            dst[tid + 256] = wn1;
        }
        __syncthreads();
    }

    // ---- accumulators -> smem scores ----
    #pragma unroll
    for (int j = 0; j < 16; j++) {
        float2 v = ull_as_f2(acc[j]);
        *(float2*)(sc + tp * SSTR + half * 32 + 2 * j) = v;
    }
    __syncthreads();

    // ---- per-token epilogue: softmax + top-8 ----
    if (tid < BT) {
        float* row = sc + tid * SSTR;
        float m = -3.4e38f;
        #pragma unroll
        for (int e = 0; e < NE; e++) {
            float v = row[e] + bias_s[e];
            row[e] = v;
            m = fmaxf(m, v);
        }
        float z = 0.0f;
        #pragma unroll
        for (int e = 0; e < NE; e++)
            z += exp2f((row[e] - m) * LOG2E);
        float invz = 1.0f / z;

        unsigned long long msk = 0ull;
        float tw[TOPK]; int ti[TOPK];
        float ts = 0.0f;
        #pragma unroll 1
        for (int it = 0; it < TOPK; it++) {
            float bv = -3.4e38f; int bi = 0;
            #pragma unroll
            for (int e = 0; e < NE; e++) {
                float v = row[e];
                bool ok = (((msk >> e) & 1ull) == 0ull) && (v > bv);
                if (ok) { bv = v; bi = e; }
            }
            msk |= 1ull << bi;
            float p = exp2f((bv - m) * LOG2E) * invz;
            ts += p; tw[it] = p; ti[it] = bi;
        }
        float inv = 1.0f / (ts + 1e-8f);

        const long long tok = tb + tid;
        float* ow = out + tok * TOPK;
        float* oi = out + (long long)T * TOPK + tok * TOPK;
        *(float4*)(ow)     = make_float4(tw[0]*inv, tw[1]*inv, tw[2]*inv, tw[3]*inv);
        *(float4*)(ow + 4) = make_float4(tw[4]*inv, tw[5]*inv, tw[6]*inv, tw[7]*inv);
        *(float4*)(oi)     = make_float4((float)ti[0], (float)ti[1], (float)ti[2], (float)ti[3]);
        *(float4*)(oi + 4) = make_float4((float)ti[4], (float)ti[5], (float)ti[6], (float)ti[7]);
        #pragma unroll
        for (int k = 0; k < TOPK; k++) atomicAdd(&hist_s[ti[k]], 1);
    }
    __syncthreads();

    if (tid < NE) {
        atomicAdd(&g_hist[tid], hist_s[tid]);
        __threadfence();
    }
    __syncthreads();

    // ---- last-CTA finalize ----
    if (tid == 0) {
        int t = atomicAdd(&g_cnt, 1);
        *flag_s = (t == (int)gridDim.x - 1) ? 1 : 0;
    }
    __syncthreads();
    if (*flag_s) {
        __threadfence();
        if (tid < NE) {
            int cnt = atomicAdd(&g_hist[tid], 0);
            float u = (float)cnt * inv_total;
            float* out_bias  = out + 2LL * T * TOPK;
            float* out_usage = out_bias + NE;
            out_bias[tid]  = bias_in[tid] - 0.01f * (u - 1.0f / (float)NE);
            out_usage[tid] = 0.9f * usage_in[tid] + 0.1f * u;
        }
        if (tid == 0) atomicExch(&g_cnt, 0);
    }
}

// ============================================================
extern "C" void kernel_launch(void* const* d_in, const int* in_sizes, int n_in,
                              void* d_out, int out_size) {
    const float* x     = (const float*)d_in[0];   // [4, 8192, 2048]
    const float* gw    = (const float*)d_in[1];   // [64, 2048]
    const float* bias  = (const float*)d_in[2];   // [64]
    const float* usage = (const float*)d_in[3];   // [64]

    const int T = in_sizes[0] / DIM;              // 32768
    float* out = (float*)d_out;

    const int smem_bytes = (4096 + BT * SSTR + NE) * 4 + NE * 4 + 16;
    cudaFuncSetAttribute(gate_kernel,
                         cudaFuncAttributeMaxDynamicSharedMemorySize, smem_bytes);

    prep_kernel<<<32, 256>>>(gw);
    gate_kernel<<<T / BT, NTHR, smem_bytes>>>(x, bias, usage, out, T,
                                              1.0f / (float)(T * TOPK));
}

// round 7
// speedup vs baseline: 1.0129x; 1.0129x over previous
#include <cuda_runtime.h>
#include <stdint.h>

#define DIM   2048
#define NE    64
#define TOPK  8
#define BT    128            // tokens per CTA
#define NTHR  256
#define KC    16             // k per smem chunk
#define NCHK  (DIM / KC)     // 128
#define XSTR  264            // x smem row: 128 tokens duplicated (256) + 8 pad
#define XBUF  (KC * XSTR)    // 4224 floats
#define WBUF  (KC * NE)      // 1024 floats
#define SSTR  66
#define LOG2E 1.4426950408889634f

// Transposed weights [k][expert] as float4. 512 KB, L2-resident.
__device__ float4 g_wt4[DIM * (NE / 4)];
__device__ int    g_hist[NE];
__device__ int    g_cnt;

// ---------------- helpers ----------------
__device__ __forceinline__ void ffma2(unsigned long long &d,
                                      unsigned long long a,
                                      unsigned long long b) {
    asm("fma.rn.f32x2 %0, %1, %2, %0;" : "+l"(d) : "l"(a), "l"(b));
}
__device__ __forceinline__ float2 ull_as_f2(unsigned long long v) {
    float2 r;
    asm("mov.b64 {%0, %1}, %2;" : "=f"(r.x), "=f"(r.y) : "l"(v));
    return r;
}

// ============================================================
// Prep: transpose gate_weight [64][2048] -> g_wt4 [2048][16xf4].
// ============================================================
__global__ void prep_kernel(const float* __restrict__ gw) {
    __shared__ float ts[64][68];
    const int t = threadIdx.x, blk = blockIdx.x;
    #pragma unroll
    for (int i = 0; i < 4; i++) {
        int idx = t + i * 256;
        int e = idx >> 4, q = idx & 15;
        float4 f = ((const float4*)gw)[e * 512 + blk * 16 + q];
        ts[e][q * 4 + 0] = f.x; ts[e][q * 4 + 1] = f.y;
        ts[e][q * 4 + 2] = f.z; ts[e][q * 4 + 3] = f.w;
    }
    __syncthreads();
    #pragma unroll
    for (int i = 0; i < 4; i++) {
        int idx = t + i * 256;
        int k = idx >> 4, j = idx & 15;
        g_wt4[(blk * 64 + k) * 16 + j] =
            make_float4(ts[j * 4 + 0][k], ts[j * 4 + 1][k],
                        ts[j * 4 + 2][k], ts[j * 4 + 3][k]);
    }
    if (blk == 0 && t < NE) g_hist[t] = 0;
    if (blk == 0 && t == 0) g_cnt = 0;
}

// ============================================================
// Fused gate kernel. CTA: 128 tokens x 64 experts, 256 threads.
// Thread tile: 4 tokens x 8 experts (16 FFMA2 per k vs 4 LDS.128).
// Per-(token,expert) arithmetic: sequential fp32 FMA chain over
// k ascending — bitwise identical to the passing R1/R6 kernels.
// ============================================================
__global__ void __launch_bounds__(NTHR, 2)
gate_kernel(const float* __restrict__ x,
            const float* __restrict__ bias_in,
            const float* __restrict__ usage_in,
            float* __restrict__ out, int T, float inv_total) {
    extern __shared__ float sm[];
    float* xsm    = sm;                    // [2][XBUF] = 8448 floats
    float* wsm    = sm + 2 * XBUF;         // [2][WBUF] = 2048 floats
    float* sc     = sm;                    // [128][66] — reuses pipeline bufs
    float* bias_s = sm + 2 * XBUF + 2 * WBUF;   // [64]
    int*   hist_s = (int*)(bias_s + NE);        // [64]
    int*   flag_s = hist_s + NE;

    const int tid  = threadIdx.x;
    const int eg   = tid & 7;              // expert group: experts eg*8..+7
    const int tg   = tid >> 3;             // token group:  tokens tg*4..+3
    const int tks  = tid >> 1;             // staging token (0..127)
    const int sub  = tid & 1;              // staging k-sub
    const long long tb = (long long)blockIdx.x * BT;

    if (tid < NE) { hist_s[tid] = 0; bias_s[tid] = bias_in[tid]; }

    const float* xg = x + (tb + tks) * (long long)DIM + sub * 4;

    // ---- stage chunk 0 ----
    {
        float4 a = *(const float4*)(xg);
        float4 b = *(const float4*)(xg + 8);
        float va[4] = {a.x, a.y, a.z, a.w};
        float vb[4] = {b.x, b.y, b.z, b.w};
        #pragma unroll
        for (int j = 0; j < 4; j++) {
            *(float2*)(xsm + (sub * 4 + j) * XSTR + tks * 2) =
                make_float2(va[j], va[j]);
            *(float2*)(xsm + (sub * 4 + 8 + j) * XSTR + tks * 2) =
                make_float2(vb[j], vb[j]);
        }
        ((float4*)wsm)[tid] = g_wt4[tid];
    }

    unsigned long long acc[4][4];
    #pragma unroll
    for (int t = 0; t < 4; t++)
        #pragma unroll
        for (int j = 0; j < 4; j++) acc[t][j] = 0ull;

    __syncthreads();

    for (int ch = 0; ch < NCHK; ch++) {
        const int buf = ch & 1;

        // prefetch next chunk into regs
        float4 xa, xb, wn;
        if (ch + 1 < NCHK) {
            xa = *(const float4*)(xg + (ch + 1) * KC);
            xb = *(const float4*)(xg + (ch + 1) * KC + 8);
            wn = g_wt4[(ch + 1) * (KC * 16) + tid];
        }

        const float* xbp = xsm + buf * XBUF + tg * 8;
        const float* wbp = wsm + buf * WBUF + eg * 8;

        #pragma unroll
        for (int k = 0; k < KC; k++) {
            ulonglong2 xp0 = *(const ulonglong2*)(xbp + k * XSTR);
            ulonglong2 xp1 = *(const ulonglong2*)(xbp + k * XSTR + 4);
            ulonglong2 w01 = *(const ulonglong2*)(wbp + k * NE);
            ulonglong2 w23 = *(const ulonglong2*)(wbp + k * NE + 4);
            ffma2(acc[0][0], xp0.x, w01.x); ffma2(acc[0][1], xp0.x, w01.y);
            ffma2(acc[0][2], xp0.x, w23.x); ffma2(acc[0][3], xp0.x, w23.y);
            ffma2(acc[1][0], xp0.y, w01.x); ffma2(acc[1][1], xp0.y, w01.y);
            ffma2(acc[1][2], xp0.y, w23.x); ffma2(acc[1][3], xp0.y, w23.y);
            ffma2(acc[2][0], xp1.x, w01.x); ffma2(acc[2][1], xp1.x, w01.y);
            ffma2(acc[2][2], xp1.x, w23.x); ffma2(acc[2][3], xp1.x, w23.y);
            ffma2(acc[3][0], xp1.y, w01.x); ffma2(acc[3][1], xp1.y, w01.y);
            ffma2(acc[3][2], xp1.y, w23.x); ffma2(acc[3][3], xp1.y, w23.y);
        }

        // stage next chunk into the other buffer
        if (ch + 1 < NCHK) {
            float* xd = xsm + (buf ^ 1) * XBUF;
            float va[4] = {xa.x, xa.y, xa.z, xa.w};
            float vb[4] = {xb.x, xb.y, xb.z, xb.w};
            #pragma unroll
            for (int j = 0; j < 4; j++) {
                *(float2*)(xd + (sub * 4 + j) * XSTR + tks * 2) =
                    make_float2(va[j], va[j]);
                *(float2*)(xd + (sub * 4 + 8 + j) * XSTR + tks * 2) =
                    make_float2(vb[j], vb[j]);
            }
            ((float4*)(wsm + (buf ^ 1) * WBUF))[tid] = wn;
        }
        __syncthreads();
    }

    // ---- accumulators -> smem scores (pipeline buffers are dead) ----
    #pragma unroll
    for (int t = 0; t < 4; t++) {
        #pragma unroll
        for (int j = 0; j < 4; j++) {
            float2 v = ull_as_f2(acc[t][j]);
            *(float2*)(sc + (tg * 4 + t) * SSTR + eg * 8 + 2 * j) = v;
        }
    }
    __syncthreads();

    // ---- per-token epilogue: softmax + top-8 ----
    if (tid < BT) {
        float* row = sc + tid * SSTR;
        float m = -3.4e38f;
        #pragma unroll
        for (int e = 0; e < NE; e++) {
            float v = row[e] + bias_s[e];
            row[e] = v;
            m = fmaxf(m, v);
        }
        float z = 0.0f;
        #pragma unroll
        for (int e = 0; e < NE; e++)
            z += exp2f((row[e] - m) * LOG2E);
        float invz = 1.0f / z;

        unsigned long long msk = 0ull;
        float tw[TOPK]; int ti[TOPK];
        float ts = 0.0f;
        #pragma unroll 1
        for (int it = 0; it < TOPK; it++) {
            float bv = -3.4e38f; int bi = 0;
            #pragma unroll
            for (int e = 0; e < NE; e++) {
                float v = row[e];
                bool ok = (((msk >> e) & 1ull) == 0ull) && (v > bv);
                if (ok) { bv = v; bi = e; }
            }
            msk |= 1ull << bi;
            float p = exp2f((bv - m) * LOG2E) * invz;
            ts += p; tw[it] = p; ti[it] = bi;
        }
        float inv = 1.0f / (ts + 1e-8f);

        const long long tok = tb + tid;
        float* ow = out + tok * TOPK;
        float* oi = out + (long long)T * TOPK + tok * TOPK;
        *(float4*)(ow)     = make_float4(tw[0]*inv, tw[1]*inv, tw[2]*inv, tw[3]*inv);
        *(float4*)(ow + 4) = make_float4(tw[4]*inv, tw[5]*inv, tw[6]*inv, tw[7]*inv);
        *(float4*)(oi)     = make_float4((float)ti[0], (float)ti[1], (float)ti[2], (float)ti[3]);
        *(float4*)(oi + 4) = make_float4((float)ti[4], (float)ti[5], (float)ti[6], (float)ti[7]);
        #pragma unroll
        for (int k = 0; k < TOPK; k++) atomicAdd(&hist_s[ti[k]], 1);
    }
    __syncthreads();

    if (tid < NE) {
        atomicAdd(&g_hist[tid], hist_s[tid]);
        __threadfence();
    }
    __syncthreads();

    // ---- last-CTA finalize ----
    if (tid == 0) {
        int t = atomicAdd(&g_cnt, 1);
        *flag_s = (t == (int)gridDim.x - 1) ? 1 : 0;
    }
    __syncthreads();
    if (*flag_s) {
        __threadfence();
        if (tid < NE) {
            int cnt = atomicAdd(&g_hist[tid], 0);
            float u = (float)cnt * inv_total;
            float* out_bias  = out + 2LL * T * TOPK;
            float* out_usage = out_bias + NE;
            out_bias[tid]  = bias_in[tid] - 0.01f * (u - 1.0f / (float)NE);
            out_usage[tid] = 0.9f * usage_in[tid] + 0.1f * u;
        }
        if (tid == 0) atomicExch(&g_cnt, 0);
    }
}

// ============================================================
extern "C" void kernel_launch(void* const* d_in, const int* in_sizes, int n_in,
                              void* d_out, int out_size) {
    const float* x     = (const float*)d_in[0];   // [4, 8192, 2048]
    const float* gw    = (const float*)d_in[1];   // [64, 2048]
    const float* bias  = (const float*)d_in[2];   // [64]
    const float* usage = (const float*)d_in[3];   // [64]

    const int T = in_sizes[0] / DIM;              // 32768
    float* out = (float*)d_out;

    const int smem_bytes = (2 * XBUF + 2 * WBUF + NE) * 4 + NE * 4 + 16;
    cudaFuncSetAttribute(gate_kernel,
                         cudaFuncAttributeMaxDynamicSharedMemorySize, smem_bytes);

    prep_kernel<<<32, 256>>>(gw);
    gate_kernel<<<T / BT, NTHR, smem_bytes>>>(x, bias, usage, out, T,
                                              1.0f / (float)(T * TOPK));
}

// round 8
// speedup vs baseline: 1.3777x; 1.3601x over previous
#include <cuda_runtime.h>
#include <stdint.h>

#define DIM   2048
#define NE    64
#define TOPK  8
#define BT    256            // tokens per CTA
#define NTHR  256
#define KC    32             // k per smem chunk
#define NCHK  (DIM / KC)     // 64
#define XB    (KC * BT)      // 8192 floats per x buffer
#define WB    (KC * NE)      // 2048 floats per w buffer
#define SSTR  66
#define LOG2E 1.4426950408889634f

// Transposed weights [k][expert] as float4. 512 KB, L2-resident.
__device__ float4 g_wt4[DIM * (NE / 4)];
__device__ int    g_hist[NE];
__device__ int    g_cnt;

// ---------------- helpers ----------------
__device__ __forceinline__ void ffma2(unsigned long long &d,
                                      unsigned long long a,
                                      unsigned long long b) {
    asm("fma.rn.f32x2 %0, %1, %2, %0;" : "+l"(d) : "l"(a), "l"(b));
}
__device__ __forceinline__ unsigned long long dup2(float w) {
    unsigned long long r;
    asm("mov.b64 %0, {%1, %1};" : "=l"(r) : "f"(w));
    return r;
}
__device__ __forceinline__ float2 ull_as_f2(unsigned long long v) {
    float2 r;
    asm("mov.b64 {%0, %1}, %2;" : "=f"(r.x), "=f"(r.y) : "l"(v));
    return r;
}

// ============================================================
// Prep: transpose gate_weight [64][2048] -> g_wt4 [2048][16xf4].
// ============================================================
__global__ void prep_kernel(const float* __restrict__ gw) {
    __shared__ float ts[64][68];
    const int t = threadIdx.x, blk = blockIdx.x;
    #pragma unroll
    for (int i = 0; i < 4; i++) {
        int idx = t + i * 256;
        int e = idx >> 4, q = idx & 15;
        float4 f = ((const float4*)gw)[e * 512 + blk * 16 + q];
        ts[e][q * 4 + 0] = f.x; ts[e][q * 4 + 1] = f.y;
        ts[e][q * 4 + 2] = f.z; ts[e][q * 4 + 3] = f.w;
    }
    __syncthreads();
    #pragma unroll
    for (int i = 0; i < 4; i++) {
        int idx = t + i * 256;
        int k = idx >> 4, j = idx & 15;
        g_wt4[(blk * 64 + k) * 16 + j] =
            make_float4(ts[j * 4 + 0][k], ts[j * 4 + 1][k],
                        ts[j * 4 + 2][k], ts[j * 4 + 3][k]);
    }
    if (blk == 0 && t < NE) g_hist[t] = 0;
    if (blk == 0 && t == 0) g_cnt = 0;
}

// ============================================================
// Fused gate kernel. CTA: 256 tokens x 64 experts, 256 threads,
// grid 128 (1 CTA/SM). Thread tile 8 tok x 8 exp: per k reads
// 32B x + 32B w from smem for 32 FFMA2 (64B per FFMA2-warp-instr
// = L1 return bus balanced against fma peak). Token pairs packed
// in f32x2; w duplicated in registers (alu pipe).
// Per-(token,expert): sequential fp32 FMA chain, k ascending —
// bitwise identical to the passing R1/R6/R7 kernels.
// ============================================================
__global__ void __launch_bounds__(NTHR, 1)
gate_kernel(const float* __restrict__ x,
            const float* __restrict__ bias_in,
            const float* __restrict__ usage_in,
            float* __restrict__ out, int T, float inv_total) {
    extern __shared__ float sm[];
    float* xsm    = sm;                        // [2][KC][256] = 16384 f
    float* wsm    = sm + 2 * XB;               // [2][KC][64]  = 4096 f
    float* sc     = sm;                        // [256][66] — aliases bufs
    float* bias_s = sm + 2 * XB + 2 * WB;      // [64]
    int*   hist_s = (int*)(bias_s + NE);       // [64]
    int*   flag_s = hist_s + NE;

    const int tid = threadIdx.x;
    const int tg  = tid >> 3;                  // token group (8 tokens)
    const int eg  = tid & 7;                   // expert group (8 experts)
    const long long tb = (long long)blockIdx.x * BT;

    if (tid < NE) { hist_s[tid] = 0; bias_s[tid] = bias_in[tid]; }

    const float* xg = x + (tb + tid) * (long long)DIM;  // staging token = tid

    // ---- stage chunk 0 ----
    {
        #pragma unroll
        for (int i = 0; i < 8; i++) {
            float4 v = *(const float4*)(xg + i * 4);
            xsm[(i * 4 + 0) * BT + tid] = v.x;
            xsm[(i * 4 + 1) * BT + tid] = v.y;
            xsm[(i * 4 + 2) * BT + tid] = v.z;
            xsm[(i * 4 + 3) * BT + tid] = v.w;
        }
        ((float4*)wsm)[tid]       = g_wt4[tid];
        ((float4*)wsm)[tid + 256] = g_wt4[tid + 256];
    }

    unsigned long long acc[4][8];
    #pragma unroll
    for (int tp = 0; tp < 4; tp++)
        #pragma unroll
        for (int e = 0; e < 8; e++) acc[tp][e] = 0ull;

    __syncthreads();

    for (int ch = 0; ch < NCHK; ch++) {
        const int buf = ch & 1;

        // prefetch next chunk into regs
        float4 xn0, xn1, xn2, xn3, xn4, xn5, xn6, xn7, wn0, wn1;
        if (ch + 1 < NCHK) {
            const float* xp = xg + (ch + 1) * KC;
            xn0 = *(const float4*)(xp);      xn1 = *(const float4*)(xp + 4);
            xn2 = *(const float4*)(xp + 8);  xn3 = *(const float4*)(xp + 12);
            xn4 = *(const float4*)(xp + 16); xn5 = *(const float4*)(xp + 20);
            xn6 = *(const float4*)(xp + 24); xn7 = *(const float4*)(xp + 28);
            wn0 = g_wt4[(ch + 1) * 512 + tid];
            wn1 = g_wt4[(ch + 1) * 512 + 256 + tid];
        }

        const float* xb = xsm + buf * XB + tg * 8;
        const float* wb = wsm + buf * WB + eg * 8;

        #pragma unroll 4
        for (int k = 0; k < KC; k++) {
            ulonglong2 xa = *(const ulonglong2*)(xb + k * BT);
            ulonglong2 xc = *(const ulonglong2*)(xb + k * BT + 4);
            float4 w0 = *(const float4*)(wb + k * NE);
            float4 w1 = *(const float4*)(wb + k * NE + 4);
            unsigned long long wd[8];
            wd[0] = dup2(w0.x); wd[1] = dup2(w0.y);
            wd[2] = dup2(w0.z); wd[3] = dup2(w0.w);
            wd[4] = dup2(w1.x); wd[5] = dup2(w1.y);
            wd[6] = dup2(w1.z); wd[7] = dup2(w1.w);
            #pragma unroll
            for (int e = 0; e < 8; e++) {
                ffma2(acc[0][e], xa.x, wd[e]);
                ffma2(acc[1][e], xa.y, wd[e]);
                ffma2(acc[2][e], xc.x, wd[e]);
                ffma2(acc[3][e], xc.y, wd[e]);
            }
        }

        // stage next chunk into the other buffer
        if (ch + 1 < NCHK) {
            float* xd = xsm + (buf ^ 1) * XB;
            float4 vv[8] = {xn0, xn1, xn2, xn3, xn4, xn5, xn6, xn7};
            #pragma unroll
            for (int i = 0; i < 8; i++) {
                xd[(i * 4 + 0) * BT + tid] = vv[i].x;
                xd[(i * 4 + 1) * BT + tid] = vv[i].y;
                xd[(i * 4 + 2) * BT + tid] = vv[i].z;
                xd[(i * 4 + 3) * BT + tid] = vv[i].w;
            }
            float4* wdst = (float4*)(wsm + (buf ^ 1) * WB);
            wdst[tid]       = wn0;
            wdst[tid + 256] = wn1;
        }
        __syncthreads();
    }

    // ---- accumulators -> smem scores (pipeline bufs are dead) ----
    #pragma unroll
    for (int tp = 0; tp < 4; tp++) {
        #pragma unroll
        for (int e = 0; e < 8; e++) {
            float2 v = ull_as_f2(acc[tp][e]);
            sc[(tg * 8 + tp * 2) * SSTR + eg * 8 + e]     = v.x;
            sc[(tg * 8 + tp * 2 + 1) * SSTR + eg * 8 + e] = v.y;
        }
    }
    __syncthreads();

    // ---- per-token epilogue: softmax + top-8 ----
    {
        float* row = sc + tid * SSTR;
        float m = -3.4e38f;
        #pragma unroll
        for (int e = 0; e < NE; e++) {
            float v = row[e] + bias_s[e];
            row[e] = v;
            m = fmaxf(m, v);
        }
        float z = 0.0f;
        #pragma unroll
        for (int e = 0; e < NE; e++)
            z += exp2f((row[e] - m) * LOG2E);
        float invz = 1.0f / z;

        unsigned long long msk = 0ull;
        float tw[TOPK]; int ti[TOPK];
        float ts = 0.0f;
        #pragma unroll 1
        for (int it = 0; it < TOPK; it++) {
            float bv = -3.4e38f; int bi = 0;
            #pragma unroll
            for (int e = 0; e < NE; e++) {
                float v = row[e];
                bool ok = (((msk >> e) & 1ull) == 0ull) && (v > bv);
                if (ok) { bv = v; bi = e; }
            }
            msk |= 1ull << bi;
            float p = exp2f((bv - m) * LOG2E) * invz;
            ts += p; tw[it] = p; ti[it] = bi;
        }
        float inv = 1.0f / (ts + 1e-8f);

        const long long tok = tb + tid;
        float* ow = out + tok * TOPK;
        float* oi = out + (long long)T * TOPK + tok * TOPK;
        *(float4*)(ow)     = make_float4(tw[0]*inv, tw[1]*inv, tw[2]*inv, tw[3]*inv);
        *(float4*)(ow + 4) = make_float4(tw[4]*inv, tw[5]*inv, tw[6]*inv, tw[7]*inv);
        *(float4*)(oi)     = make_float4((float)ti[0], (float)ti[1], (float)ti[2], (float)ti[3]);
        *(float4*)(oi + 4) = make_float4((float)ti[4], (float)ti[5], (float)ti[6], (float)ti[7]);
        #pragma unroll
        for (int k = 0; k < TOPK; k++) atomicAdd(&hist_s[ti[k]], 1);
    }
    __syncthreads();

    if (tid < NE) {
        atomicAdd(&g_hist[tid], hist_s[tid]);
        __threadfence();
    }
    __syncthreads();

    // ---- last-CTA finalize ----
    if (tid == 0) {
        int t = atomicAdd(&g_cnt, 1);
        *flag_s = (t == (int)gridDim.x - 1) ? 1 : 0;
    }
    __syncthreads();
    if (*flag_s) {
        __threadfence();
        if (tid < NE) {
            int cnt = atomicAdd(&g_hist[tid], 0);
            float u = (float)cnt * inv_total;
            float* out_bias  = out + 2LL * T * TOPK;
            float* out_usage = out_bias + NE;
            out_bias[tid]  = bias_in[tid] - 0.01f * (u - 1.0f / (float)NE);
            out_usage[tid] = 0.9f * usage_in[tid] + 0.1f * u;
        }
        if (tid == 0) atomicExch(&g_cnt, 0);
    }
}

// ============================================================
extern "C" void kernel_launch(void* const* d_in, const int* in_sizes, int n_in,
                              void* d_out, int out_size) {
    const float* x     = (const float*)d_in[0];   // [4, 8192, 2048]
    const float* gw    = (const float*)d_in[1];   // [64, 2048]
    const float* bias  = (const float*)d_in[2];   // [64]
    const float* usage = (const float*)d_in[3];   // [64]

    const int T = in_sizes[0] / DIM;              // 32768
    float* out = (float*)d_out;

    const int smem_bytes = (2 * XB + 2 * WB + NE) * 4 + NE * 4 + 16;
    cudaFuncSetAttribute(gate_kernel,
                         cudaFuncAttributeMaxDynamicSharedMemorySize, smem_bytes);

    prep_kernel<<<32, 256>>>(gw);
    gate_kernel<<<T / BT, NTHR, smem_bytes>>>(x, bias, usage, out, T,
                                              1.0f / (float)(T * TOPK));
}

// round 9
// speedup vs baseline: 1.4757x; 1.0712x over previous
#include <cuda_runtime.h>
#include <stdint.h>

#define DIM   2048
#define NE    64
#define TOPK  8
#define BT    256            // tokens per CTA
#define NTHR  256
#define KC    32             // k per smem chunk
#define NCHK  (DIM / KC)     // 64
#define XB    (KC * BT)      // 8192 floats per x buffer
#define WB    (KC * NE)      // 2048 floats per w buffer
#define SSTR  66
#define LOG2E 1.4426950408889634f

// Transposed weights [k][expert] as float4. 512 KB, L2-resident.
__device__ float4 g_wt4[DIM * (NE / 4)];
__device__ int    g_hist[NE];
__device__ int    g_cnt;

// ---------------- helpers ----------------
__device__ __forceinline__ void ffma2(unsigned long long &d,
                                      unsigned long long a,
                                      unsigned long long b) {
    asm("fma.rn.f32x2 %0, %1, %2, %0;" : "+l"(d) : "l"(a), "l"(b));
}
__device__ __forceinline__ unsigned long long dup2(float w) {
    unsigned long long r;
    asm("mov.b64 %0, {%1, %1};" : "=l"(r) : "f"(w));
    return r;
}
__device__ __forceinline__ float2 ull_as_f2(unsigned long long v) {
    float2 r;
    asm("mov.b64 {%0, %1}, %2;" : "=f"(r.x), "=f"(r.y) : "l"(v));
    return r;
}

// ============================================================
// Prep: transpose gate_weight [64][2048] -> g_wt4 [2048][16xf4].
// ============================================================
__global__ void prep_kernel(const float* __restrict__ gw) {
    __shared__ float ts[64][68];
    const int t = threadIdx.x, blk = blockIdx.x;
    #pragma unroll
    for (int i = 0; i < 4; i++) {
        int idx = t + i * 256;
        int e = idx >> 4, q = idx & 15;
        float4 f = ((const float4*)gw)[e * 512 + blk * 16 + q];
        ts[e][q * 4 + 0] = f.x; ts[e][q * 4 + 1] = f.y;
        ts[e][q * 4 + 2] = f.z; ts[e][q * 4 + 3] = f.w;
    }
    __syncthreads();
    #pragma unroll
    for (int i = 0; i < 4; i++) {
        int idx = t + i * 256;
        int k = idx >> 4, j = idx & 15;
        g_wt4[(blk * 64 + k) * 16 + j] =
            make_float4(ts[j * 4 + 0][k], ts[j * 4 + 1][k],
                        ts[j * 4 + 2][k], ts[j * 4 + 3][k]);
    }
    if (blk == 0 && t < NE) g_hist[t] = 0;
    if (blk == 0 && t == 0) g_cnt = 0;
}

// one k-step: 8 dup MOVs (alu pipe) + 32 FFMA2 (fma pipe)
#define COMPUTE_K(XA, XC, W0, W1)                                  \
    do {                                                           \
        unsigned long long wd0 = dup2((W0).x), wd1 = dup2((W0).y); \
        unsigned long long wd2 = dup2((W0).z), wd3 = dup2((W0).w); \
        unsigned long long wd4 = dup2((W1).x), wd5 = dup2((W1).y); \
        unsigned long long wd6 = dup2((W1).z), wd7 = dup2((W1).w); \
        ffma2(acc[0][0], (XA).x, wd0); ffma2(acc[1][0], (XA).y, wd0); \
        ffma2(acc[2][0], (XC).x, wd0); ffma2(acc[3][0], (XC).y, wd0); \
        ffma2(acc[0][1], (XA).x, wd1); ffma2(acc[1][1], (XA).y, wd1); \
        ffma2(acc[2][1], (XC).x, wd1); ffma2(acc[3][1], (XC).y, wd1); \
        ffma2(acc[0][2], (XA).x, wd2); ffma2(acc[1][2], (XA).y, wd2); \
        ffma2(acc[2][2], (XC).x, wd2); ffma2(acc[3][2], (XC).y, wd2); \
        ffma2(acc[0][3], (XA).x, wd3); ffma2(acc[1][3], (XA).y, wd3); \
        ffma2(acc[2][3], (XC).x, wd3); ffma2(acc[3][3], (XC).y, wd3); \
        ffma2(acc[0][4], (XA).x, wd4); ffma2(acc[1][4], (XA).y, wd4); \
        ffma2(acc[2][4], (XC).x, wd4); ffma2(acc[3][4], (XC).y, wd4); \
        ffma2(acc[0][5], (XA).x, wd5); ffma2(acc[1][5], (XA).y, wd5); \
        ffma2(acc[2][5], (XC).x, wd5); ffma2(acc[3][5], (XC).y, wd5); \
        ffma2(acc[0][6], (XA).x, wd6); ffma2(acc[1][6], (XA).y, wd6); \
        ffma2(acc[2][6], (XC).x, wd6); ffma2(acc[3][6], (XC).y, wd6); \
        ffma2(acc[0][7], (XA).x, wd7); ffma2(acc[1][7], (XA).y, wd7); \
        ffma2(acc[2][7], (XC).x, wd7); ffma2(acc[3][7], (XC).y, wd7); \
    } while (0)

// ============================================================
// Fused gate kernel. CTA: 256 tok x 64 exp, 256 threads, grid 128.
// Thread tile 8 tok x 8 exp (L1-return / fma balanced). Inner loop
// software-pipelined: k+1 operands load before k's FFMA block.
// Per-(token,expert): sequential fp32 FMA chain, k ascending —
// bitwise identical to R1/R6/R7/R8.
// ============================================================
__global__ void __launch_bounds__(NTHR, 1)
gate_kernel(const float* __restrict__ x,
            const float* __restrict__ bias_in,
            const float* __restrict__ usage_in,
            float* __restrict__ out, int T, float inv_total) {
    extern __shared__ float sm[];
    float* xsm    = sm;                        // [2][KC][256] = 16384 f
    float* wsm    = sm + 2 * XB;               // [2][KC][64]  = 4096 f
    float* sc     = sm;                        // [256][66] — aliases bufs
    float* bias_s = sm + 2 * XB + 2 * WB;      // [64]
    int*   hist_s = (int*)(bias_s + NE);       // [64]
    int*   flag_s = hist_s + NE;

    const int tid = threadIdx.x;
    const int tg  = tid >> 3;                  // token group (8 tokens)
    const int eg  = tid & 7;                   // expert group (8 experts)
    const long long tb = (long long)blockIdx.x * BT;

    if (tid < NE) { hist_s[tid] = 0; bias_s[tid] = bias_in[tid]; }

    const float* xg = x + (tb + tid) * (long long)DIM;  // staging token = tid

    // ---- stage chunk 0 ----
    {
        #pragma unroll
        for (int i = 0; i < 8; i++) {
            float4 v = *(const float4*)(xg + i * 4);
            xsm[(i * 4 + 0) * BT + tid] = v.x;
            xsm[(i * 4 + 1) * BT + tid] = v.y;
            xsm[(i * 4 + 2) * BT + tid] = v.z;
            xsm[(i * 4 + 3) * BT + tid] = v.w;
        }
        ((float4*)wsm)[tid]       = g_wt4[tid];
        ((float4*)wsm)[tid + 256] = g_wt4[tid + 256];
    }

    unsigned long long acc[4][8];
    #pragma unroll
    for (int tp = 0; tp < 4; tp++)
        #pragma unroll
        for (int e = 0; e < 8; e++) acc[tp][e] = 0ull;

    __syncthreads();

    for (int ch = 0; ch < NCHK; ch++) {
        const int buf = ch & 1;

        // gmem prefetch of next chunk (front-batched; consumed at tail)
        float4 xn0, xn1, xn2, xn3, xn4, xn5, xn6, xn7, wn0, wn1;
        if (ch + 1 < NCHK) {
            const float* xp = xg + (ch + 1) * KC;
            xn0 = *(const float4*)(xp);      xn1 = *(const float4*)(xp + 4);
            xn2 = *(const float4*)(xp + 8);  xn3 = *(const float4*)(xp + 12);
            xn4 = *(const float4*)(xp + 16); xn5 = *(const float4*)(xp + 20);
            xn6 = *(const float4*)(xp + 24); xn7 = *(const float4*)(xp + 28);
            wn0 = g_wt4[(ch + 1) * 512 + tid];
            wn1 = g_wt4[(ch + 1) * 512 + 256 + tid];
        }

        const float* xb = xsm + buf * XB + tg * 8;
        const float* wb = wsm + buf * WB + eg * 8;

        // software-pipelined inner loop: 1-k operand double buffer
        ulonglong2 xa = *(const ulonglong2*)(xb);
        ulonglong2 xc = *(const ulonglong2*)(xb + 4);
        float4 w0 = *(const float4*)(wb);
        float4 w1 = *(const float4*)(wb + 4);

        #pragma unroll
        for (int k = 0; k < KC - 1; k++) {
            ulonglong2 xa2 = *(const ulonglong2*)(xb + (k + 1) * BT);
            ulonglong2 xc2 = *(const ulonglong2*)(xb + (k + 1) * BT + 4);
            float4 v0 = *(const float4*)(wb + (k + 1) * NE);
            float4 v1 = *(const float4*)(wb + (k + 1) * NE + 4);
            COMPUTE_K(xa, xc, w0, w1);
            xa = xa2; xc = xc2; w0 = v0; w1 = v1;
        }
        COMPUTE_K(xa, xc, w0, w1);   // peeled last k

        // stage next chunk into the other buffer
        if (ch + 1 < NCHK) {
            float* xd = xsm + (buf ^ 1) * XB;
            float4 vv[8] = {xn0, xn1, xn2, xn3, xn4, xn5, xn6, xn7};
            #pragma unroll
            for (int i = 0; i < 8; i++) {
                xd[(i * 4 + 0) * BT + tid] = vv[i].x;
                xd[(i * 4 + 1) * BT + tid] = vv[i].y;
                xd[(i * 4 + 2) * BT + tid] = vv[i].z;
                xd[(i * 4 + 3) * BT + tid] = vv[i].w;
            }
            float4* wdst = (float4*)(wsm + (buf ^ 1) * WB);
            wdst[tid]       = wn0;
            wdst[tid + 256] = wn1;
        }
        __syncthreads();
    }

    // ---- accumulators -> smem scores (pipeline bufs are dead) ----
    #pragma unroll
    for (int tp = 0; tp < 4; tp++) {
        #pragma unroll
        for (int e = 0; e < 8; e++) {
            float2 v = ull_as_f2(acc[tp][e]);
            sc[(tg * 8 + tp * 2) * SSTR + eg * 8 + e]     = v.x;
            sc[(tg * 8 + tp * 2 + 1) * SSTR + eg * 8 + e] = v.y;
        }
    }
    __syncthreads();

    // ---- per-token epilogue: softmax + top-8 ----
    {
        float* row = sc + tid * SSTR;
        float m = -3.4e38f;
        #pragma unroll
        for (int e = 0; e < NE; e++) {
            float v = row[e] + bias_s[e];
            row[e] = v;
            m = fmaxf(m, v);
        }
        float z = 0.0f;
        #pragma unroll
        for (int e = 0; e < NE; e++)
            z += exp2f((row[e] - m) * LOG2E);
        float invz = 1.0f / z;

        unsigned long long msk = 0ull;
        float tw[TOPK]; int ti[TOPK];
        float ts = 0.0f;
        #pragma unroll 1
        for (int it = 0; it < TOPK; it++) {
            float bv = -3.4e38f; int bi = 0;
            #pragma unroll
            for (int e = 0; e < NE; e++) {
                float v = row[e];
                bool ok = (((msk >> e) & 1ull) == 0ull) && (v > bv);
                if (ok) { bv = v; bi = e; }
            }
            msk |= 1ull << bi;
            float p = exp2f((bv - m) * LOG2E) * invz;
            ts += p; tw[it] = p; ti[it] = bi;
        }
        float inv = 1.0f / (ts + 1e-8f);

        const long long tok = tb + tid;
        float* ow = out + tok * TOPK;
        float* oi = out + (long long)T * TOPK + tok * TOPK;
        *(float4*)(ow)     = make_float4(tw[0]*inv, tw[1]*inv, tw[2]*inv, tw[3]*inv);
        *(float4*)(ow + 4) = make_float4(tw[4]*inv, tw[5]*inv, tw[6]*inv, tw[7]*inv);
        *(float4*)(oi)     = make_float4((float)ti[0], (float)ti[1], (float)ti[2], (float)ti[3]);
        *(float4*)(oi + 4) = make_float4((float)ti[4], (float)ti[5], (float)ti[6], (float)ti[7]);
        #pragma unroll
        for (int k = 0; k < TOPK; k++) atomicAdd(&hist_s[ti[k]], 1);
    }
    __syncthreads();

    if (tid < NE) {
        atomicAdd(&g_hist[tid], hist_s[tid]);
        __threadfence();
    }
    __syncthreads();

    // ---- last-CTA finalize ----
    if (tid == 0) {
        int t = atomicAdd(&g_cnt, 1);
        *flag_s = (t == (int)gridDim.x - 1) ? 1 : 0;
    }
    __syncthreads();
    if (*flag_s) {
        __threadfence();
        if (tid < NE) {
            int cnt = atomicAdd(&g_hist[tid], 0);
            float u = (float)cnt * inv_total;
            float* out_bias  = out + 2LL * T * TOPK;
            float* out_usage = out_bias + NE;
            out_bias[tid]  = bias_in[tid] - 0.01f * (u - 1.0f / (float)NE);
            out_usage[tid] = 0.9f * usage_in[tid] + 0.1f * u;
        }
        if (tid == 0) atomicExch(&g_cnt, 0);
    }
}

// ============================================================
extern "C" void kernel_launch(void* const* d_in, const int* in_sizes, int n_in,
                              void* d_out, int out_size) {
    const float* x     = (const float*)d_in[0];   // [4, 8192, 2048]
    const float* gw    = (const float*)d_in[1];   // [64, 2048]
    const float* bias  = (const float*)d_in[2];   // [64]
    const float* usage = (const float*)d_in[3];   // [64]

    const int T = in_sizes[0] / DIM;              // 32768
    float* out = (float*)d_out;

    const int smem_bytes = (2 * XB + 2 * WB + NE) * 4 + NE * 4 + 16;
    cudaFuncSetAttribute(gate_kernel,
                         cudaFuncAttributeMaxDynamicSharedMemorySize, smem_bytes);

    prep_kernel<<<32, 256>>>(gw);
    gate_kernel<<<T / BT, NTHR, smem_bytes>>>(x, bias, usage, out, T,
                                              1.0f / (float)(T * TOPK));
}

// round 10
// speedup vs baseline: 1.6887x; 1.1444x over previous
#include <cuda_runtime.h>
#include <stdint.h>

#define DIM   2048
#define NE    64
#define TOPK  8
#define BT    256            // tokens per CTA
#define NTHR  256
#define KC    32             // k per smem chunk
#define NCHK  (DIM / KC)     // 64
#define XB    (KC * BT)      // 8192 floats per x buffer
#define WB    (KC * NE)      // 2048 floats per w buffer
#define SSTR  66
#define LOG2E 1.4426950408889634f

// Transposed + bank-permuted weights [k][slot] as float4. 512 KB, L2-resident.
// Slot p (16B) of a k-row holds experts: p<8 -> p*8+0..3 ; p>=8 -> (p-8)*8+4..7.
// => thread eg reads its 8 experts as two conflict-free LDS.128:
//    floats [eg*4 .. eg*4+3] and [32+eg*4 .. 32+eg*4+3].
__device__ float4 g_wt4[DIM * (NE / 4)];
__device__ int    g_hist[NE];
__device__ int    g_cnt;

// ---------------- helpers ----------------
__device__ __forceinline__ void ffma2(unsigned long long &d,
                                      unsigned long long a,
                                      unsigned long long b) {
    asm("fma.rn.f32x2 %0, %1, %2, %0;" : "+l"(d) : "l"(a), "l"(b));
}
__device__ __forceinline__ unsigned long long dup2(float w) {
    unsigned long long r;
    asm("mov.b64 %0, {%1, %1};" : "=l"(r) : "f"(w));
    return r;
}
__device__ __forceinline__ float2 ull_as_f2(unsigned long long v) {
    float2 r;
    asm("mov.b64 {%0, %1}, %2;" : "=f"(r.x), "=f"(r.y) : "l"(v));
    return r;
}
__device__ __forceinline__ void cp16(uint32_t dst_smem, const void* src) {
    asm volatile("cp.async.ca.shared.global [%0], [%1], 16;"
                 :: "r"(dst_smem), "l"(src));
}
__device__ __forceinline__ void cp_commit() {
    asm volatile("cp.async.commit_group;");
}
__device__ __forceinline__ void cp_wait0() {
    asm volatile("cp.async.wait_group 0;" ::: "memory");
}

// ============================================================
// Prep: transpose gate_weight [64][2048] -> g_wt4 [2048][16 slots],
// with the conflict-free slot permutation described above.
// ============================================================
__global__ void prep_kernel(const float* __restrict__ gw) {
    __shared__ float ts[64][68];
    const int t = threadIdx.x, blk = blockIdx.x;
    #pragma unroll
    for (int i = 0; i < 4; i++) {
        int idx = t + i * 256;
        int e = idx >> 4, q = idx & 15;
        float4 f = ((const float4*)gw)[e * 512 + blk * 16 + q];
        ts[e][q * 4 + 0] = f.x; ts[e][q * 4 + 1] = f.y;
        ts[e][q * 4 + 2] = f.z; ts[e][q * 4 + 3] = f.w;
    }
    __syncthreads();
    #pragma unroll
    for (int i = 0; i < 4; i++) {
        int idx = t + i * 256;
        int k = idx >> 4, p = idx & 15;               // slot p
        int base = (p < 8) ? p * 8 : (p - 8) * 8 + 4; // expert base
        g_wt4[(blk * 64 + k) * 16 + p] =
            make_float4(ts[base + 0][k], ts[base + 1][k],
                        ts[base + 2][k], ts[base + 3][k]);
    }
    if (blk == 0 && t < NE) g_hist[t] = 0;
    if (blk == 0 && t == 0) g_cnt = 0;
}

// one k-step: 8 dup MOVs (alu pipe) + 32 FFMA2 (fma pipe)
#define COMPUTE_K(XA, XC, W0, W1)                                  \
    do {                                                           \
        unsigned long long wd0 = dup2((W0).x), wd1 = dup2((W0).y); \
        unsigned long long wd2 = dup2((W0).z), wd3 = dup2((W0).w); \
        unsigned long long wd4 = dup2((W1).x), wd5 = dup2((W1).y); \
        unsigned long long wd6 = dup2((W1).z), wd7 = dup2((W1).w); \
        ffma2(acc[0][0], (XA).x, wd0); ffma2(acc[1][0], (XA).y, wd0); \
        ffma2(acc[2][0], (XC).x, wd0); ffma2(acc[3][0], (XC).y, wd0); \
        ffma2(acc[0][1], (XA).x, wd1); ffma2(acc[1][1], (XA).y, wd1); \
        ffma2(acc[2][1], (XC).x, wd1); ffma2(acc[3][1], (XC).y, wd1); \
        ffma2(acc[0][2], (XA).x, wd2); ffma2(acc[1][2], (XA).y, wd2); \
        ffma2(acc[2][2], (XC).x, wd2); ffma2(acc[3][2], (XC).y, wd2); \
        ffma2(acc[0][3], (XA).x, wd3); ffma2(acc[1][3], (XA).y, wd3); \
        ffma2(acc[2][3], (XC).x, wd3); ffma2(acc[3][3], (XC).y, wd3); \
        ffma2(acc[0][4], (XA).x, wd4); ffma2(acc[1][4], (XA).y, wd4); \
        ffma2(acc[2][4], (XC).x, wd4); ffma2(acc[3][4], (XC).y, wd4); \
        ffma2(acc[0][5], (XA).x, wd5); ffma2(acc[1][5], (XA).y, wd5); \
        ffma2(acc[2][5], (XC).x, wd5); ffma2(acc[3][5], (XC).y, wd5); \
        ffma2(acc[0][6], (XA).x, wd6); ffma2(acc[1][6], (XA).y, wd6); \
        ffma2(acc[2][6], (XC).x, wd6); ffma2(acc[3][6], (XC).y, wd6); \
        ffma2(acc[0][7], (XA).x, wd7); ffma2(acc[1][7], (XA).y, wd7); \
        ffma2(acc[2][7], (XC).x, wd7); ffma2(acc[3][7], (XC).y, wd7); \
    } while (0)

// ============================================================
// Fused gate kernel. CTA: 256 tok x 64 exp, 256 threads, grid 128.
// Thread tile 8 tok x 8 exp. w loads conflict-free (permuted rows),
// w staged via cp.async; x staged via regs+STS (transpose needed).
// Per-(token,expert): sequential fp32 FMA chain, k ascending —
// bitwise identical to R1/R6-R9.
// ============================================================
__global__ void __launch_bounds__(NTHR, 1)
gate_kernel(const float* __restrict__ x,
            const float* __restrict__ bias_in,
            const float* __restrict__ usage_in,
            float* __restrict__ out, int T, float inv_total) {
    extern __shared__ float sm[];
    float* xsm    = sm;                        // [2][KC][256] = 16384 f
    float* wsm    = sm + 2 * XB;               // [2][KC][64]  = 4096 f
    float* sc     = sm;                        // [256][66] — aliases bufs
    float* bias_s = sm + 2 * XB + 2 * WB;      // [64]
    int*   hist_s = (int*)(bias_s + NE);       // [64]
    int*   flag_s = hist_s + NE;

    const int tid = threadIdx.x;
    const int tg  = tid >> 3;                  // token group (8 tokens)
    const int eg  = tid & 7;                   // expert group (8 experts)
    const long long tb = (long long)blockIdx.x * BT;

    if (tid < NE) { hist_s[tid] = 0; bias_s[tid] = bias_in[tid]; }

    const float* xg = x + (tb + tid) * (long long)DIM;  // staging token = tid
    const uint32_t wsm_u32 = (uint32_t)__cvta_generic_to_shared(wsm);

    // ---- stage chunk 0 ----
    {
        // w via cp.async (2 x 16B per thread)
        cp16(wsm_u32 + tid * 16,              &g_wt4[tid]);
        cp16(wsm_u32 + (tid + 256) * 16,      &g_wt4[tid + 256]);
        cp_commit();
        // x via regs + transposed STS
        #pragma unroll
        for (int i = 0; i < 8; i++) {
            float4 v = *(const float4*)(xg + i * 4);
            xsm[(i * 4 + 0) * BT + tid] = v.x;
            xsm[(i * 4 + 1) * BT + tid] = v.y;
            xsm[(i * 4 + 2) * BT + tid] = v.z;
            xsm[(i * 4 + 3) * BT + tid] = v.w;
        }
    }

    unsigned long long acc[4][8];
    #pragma unroll
    for (int tp = 0; tp < 4; tp++)
        #pragma unroll
        for (int e = 0; e < 8; e++) acc[tp][e] = 0ull;

    cp_wait0();
    __syncthreads();

    for (int ch = 0; ch < NCHK; ch++) {
        const int buf = ch & 1;

        // next-chunk producers: w cp.async straight to smem, x to regs
        float4 xn0, xn1, xn2, xn3, xn4, xn5, xn6, xn7;
        if (ch + 1 < NCHK) {
            const uint32_t wdst = wsm_u32 + (buf ^ 1) * (WB * 4);
            cp16(wdst + tid * 16,         &g_wt4[(ch + 1) * 512 + tid]);
            cp16(wdst + (tid + 256) * 16, &g_wt4[(ch + 1) * 512 + 256 + tid]);
            cp_commit();
            const float* xp = xg + (ch + 1) * KC;
            xn0 = *(const float4*)(xp);      xn1 = *(const float4*)(xp + 4);
            xn2 = *(const float4*)(xp + 8);  xn3 = *(const float4*)(xp + 12);
            xn4 = *(const float4*)(xp + 16); xn5 = *(const float4*)(xp + 20);
            xn6 = *(const float4*)(xp + 24); xn7 = *(const float4*)(xp + 28);
        }

        const float* xb = xsm + buf * XB + tg * 8;
        const float* wb = wsm + buf * WB + eg * 4;   // permuted, conflict-free

        // software-pipelined inner loop: 1-k operand double buffer
        ulonglong2 xa = *(const ulonglong2*)(xb);
        ulonglong2 xc = *(const ulonglong2*)(xb + 4);
        float4 w0 = *(const float4*)(wb);
        float4 w1 = *(const float4*)(wb + 32);

        #pragma unroll
        for (int k = 0; k < KC - 1; k++) {
            ulonglong2 xa2 = *(const ulonglong2*)(xb + (k + 1) * BT);
            ulonglong2 xc2 = *(const ulonglong2*)(xb + (k + 1) * BT + 4);
            float4 v0 = *(const float4*)(wb + (k + 1) * NE);
            float4 v1 = *(const float4*)(wb + (k + 1) * NE + 32);
            COMPUTE_K(xa, xc, w0, w1);
            xa = xa2; xc = xc2; w0 = v0; w1 = v1;
        }
        COMPUTE_K(xa, xc, w0, w1);   // peeled last k

        // stage next x chunk into the other buffer
        if (ch + 1 < NCHK) {
            float* xd = xsm + (buf ^ 1) * XB;
            float4 vv[8] = {xn0, xn1, xn2, xn3, xn4, xn5, xn6, xn7};
            #pragma unroll
            for (int i = 0; i < 8; i++) {
                xd[(i * 4 + 0) * BT + tid] = vv[i].x;
                xd[(i * 4 + 1) * BT + tid] = vv[i].y;
                xd[(i * 4 + 2) * BT + tid] = vv[i].z;
                xd[(i * 4 + 3) * BT + tid] = vv[i].w;
            }
            cp_wait0();
        }
        __syncthreads();
    }

    // ---- accumulators -> smem scores (pipeline bufs are dead) ----
    #pragma unroll
    for (int tp = 0; tp < 4; tp++) {
        #pragma unroll
        for (int e = 0; e < 8; e++) {
            float2 v = ull_as_f2(acc[tp][e]);
            sc[(tg * 8 + tp * 2) * SSTR + eg * 8 + e]     = v.x;
            sc[(tg * 8 + tp * 2 + 1) * SSTR + eg * 8 + e] = v.y;
        }
    }
    __syncthreads();

    // ---- per-token epilogue: softmax + top-8 ----
    {
        float* row = sc + tid * SSTR;
        float m = -3.4e38f;
        #pragma unroll
        for (int e = 0; e < NE; e++) {
            float v = row[e] + bias_s[e];
            row[e] = v;
            m = fmaxf(m, v);
        }
        float z = 0.0f;
        #pragma unroll
        for (int e = 0; e < NE; e++)
            z += exp2f((row[e] - m) * LOG2E);
        float invz = 1.0f / z;

        unsigned long long msk = 0ull;
        float tw[TOPK]; int ti[TOPK];
        float ts = 0.0f;
        #pragma unroll 1
        for (int it = 0; it < TOPK; it++) {
            float bv = -3.4e38f; int bi = 0;
            #pragma unroll
            for (int e = 0; e < NE; e++) {
                float v = row[e];
                bool ok = (((msk >> e) & 1ull) == 0ull) && (v > bv);
                if (ok) { bv = v; bi = e; }
            }
            msk |= 1ull << bi;
            float p = exp2f((bv - m) * LOG2E) * invz;
            ts += p; tw[it] = p; ti[it] = bi;
        }
        float inv = 1.0f / (ts + 1e-8f);

        const long long tok = tb + tid;
        float* ow = out + tok * TOPK;
        float* oi = out + (long long)T * TOPK + tok * TOPK;
        *(float4*)(ow)     = make_float4(tw[0]*inv, tw[1]*inv, tw[2]*inv, tw[3]*inv);
        *(float4*)(ow + 4) = make_float4(tw[4]*inv, tw[5]*inv, tw[6]*inv, tw[7]*inv);
        *(float4*)(oi)     = make_float4((float)ti[0], (float)ti[1], (float)ti[2], (float)ti[3]);
        *(float4*)(oi + 4) = make_float4((float)ti[4], (float)ti[5], (float)ti[6], (float)ti[7]);
        #pragma unroll
        for (int k = 0; k < TOPK; k++) atomicAdd(&hist_s[ti[k]], 1);
    }
    __syncthreads();

    if (tid < NE) {
        atomicAdd(&g_hist[tid], hist_s[tid]);
        __threadfence();
    }
    __syncthreads();

    // ---- last-CTA finalize ----
    if (tid == 0) {
        int t = atomicAdd(&g_cnt, 1);
        *flag_s = (t == (int)gridDim.x - 1) ? 1 : 0;
    }
    __syncthreads();
    if (*flag_s) {
        __threadfence();
        if (tid < NE) {
            int cnt = atomicAdd(&g_hist[tid], 0);
            float u = (float)cnt * inv_total;
            float* out_bias  = out + 2LL * T * TOPK;
            float* out_usage = out_bias + NE;
            out_bias[tid]  = bias_in[tid] - 0.01f * (u - 1.0f / (float)NE);
            out_usage[tid] = 0.9f * usage_in[tid] + 0.1f * u;
        }
        if (tid == 0) atomicExch(&g_cnt, 0);
    }
}

// ============================================================
extern "C" void kernel_launch(void* const* d_in, const int* in_sizes, int n_in,
                              void* d_out, int out_size) {
    const float* x     = (const float*)d_in[0];   // [4, 8192, 2048]
    const float* gw    = (const float*)d_in[1];   // [64, 2048]
    const float* bias  = (const float*)d_in[2];   // [64]
    const float* usage = (const float*)d_in[3];   // [64]

    const int T = in_sizes[0] / DIM;              // 32768
    float* out = (float*)d_out;

    const int smem_bytes = (2 * XB + 2 * WB + NE) * 4 + NE * 4 + 16;
    cudaFuncSetAttribute(gate_kernel,
                         cudaFuncAttributeMaxDynamicSharedMemorySize, smem_bytes);

    prep_kernel<<<32, 256>>>(gw);
    gate_kernel<<<T / BT, NTHR, smem_bytes>>>(x, bias, usage, out, T,
                                              1.0f / (float)(T * TOPK));
}